// round 5
// baseline (speedup 1.0000x reference)
#include <cuda_runtime.h>

#define B_   256
#define T_   1024
#define NUM_ 126
#define L_   128
#define REPF 132   // floats per p-replica slot (528 B) -> bank skew 4 per quarter

__device__ int d_perm[B_];

// Rank-sort sequences by length (descending), deterministic, O(n^2) with n=256.
__global__ void crf_sort_kernel(const int* __restrict__ lens){
    __shared__ int sl[B_];
    int i = threadIdx.x;
    sl[i] = lens[i];
    __syncthreads();
    int v = sl[i];
    int r = 0;
    #pragma unroll 8
    for (int j = 0; j < B_; j++){
        int w = sl[j];
        r += (int)((w > v) | ((w == v) & (j < i)));
    }
    d_perm[r] = i;
}

__device__ __forceinline__ void ffma2(unsigned long long &d, unsigned long long a, unsigned long long b){
    asm volatile("fma.rn.f32x2 %0, %1, %2, %0;" : "+l"(d) : "l"(a), "l"(b));
}
__device__ __forceinline__ unsigned long long fadd2(unsigned long long a, unsigned long long b){
    unsigned long long d;
    asm volatile("add.rn.f32x2 %0, %1, %2;" : "=l"(d) : "l"(a), "l"(b));
    return d;
}

// Quarter dot: s = sum_{i<32} E[i]*p[i]; E is 16 packed f32x2 regs.
// p pointer is 16B-aligned; 8 LDS.128, all j-lanes of a given q broadcast,
// the 4 q-addresses hit disjoint bank groups (replica skew).
__device__ __forceinline__ float dot32(const float* __restrict__ p, const unsigned long long* __restrict__ E){
    const ulonglong2* pd = (const ulonglong2*)p;
    unsigned long long a0 = 0ull, a1 = 0ull, a2 = 0ull, a3 = 0ull;
    #pragma unroll
    for (int i = 0; i < 8; i += 2){
        ulonglong2 q0 = pd[i];
        ulonglong2 q1 = pd[i + 1];
        ffma2(a0, E[2*i + 0], q0.x);
        ffma2(a1, E[2*i + 1], q0.y);
        ffma2(a2, E[2*i + 2], q1.x);
        ffma2(a3, E[2*i + 3], q1.y);
    }
    unsigned long long s2 = fadd2(fadd2(a0, a1), fadd2(a2, a3));
    return __uint_as_float((unsigned)(s2 & 0xffffffffull)) +
           __uint_as_float((unsigned)(s2 >> 32));
}

__global__ void __launch_bounds__(512, 2)
crf_main_kernel(const float* __restrict__ logits,
                const int*   __restrict__ labels,
                const int*   __restrict__ lens,
                const float* __restrict__ trans,
                float*       __restrict__ out)
{
    __shared__ __align__(16) float pbuf[2][4 * REPF];
    __shared__ float red[16];
    __shared__ float red2[16];

    const int tid  = threadIdx.x;
    const int q    = tid & 3;          // quarter of the 128-wide dot
    const int j    = tid >> 2;         // label owned by this lane-quad (0..127)
    const int lane = tid & 31;
    const int w    = tid >> 5;         // warp 0..15

    // Placement-aware mapping: classic LUT pairs bid and bid+148 on one SM.
    // bid i -> rank i (long), bid 148+i -> rank 255-i (short) => long pairs with short.
    const int bid  = (int)blockIdx.x;
    const int rank = (bid < 148) ? bid : (403 - bid);
    const int seq  = d_perm[rank];
    const int len  = lens[seq];

    // ---- E quarter-row exp(Tr[j, 32q .. 32q+32)) in 16 packed f32x2 regs ----
    unsigned long long Ereg[16];
    {
        const float* trow = trans + j * L_ + 32 * q;
        #pragma unroll
        for (int m = 0; m < 16; m++){
            float e0 = expf(trow[2*m]);
            float e1 = expf(trow[2*m + 1]);
            Ereg[m] = (unsigned long long)__float_as_uint(e0)
                    | ((unsigned long long)__float_as_uint(e1) << 32);
        }
    }

    const float* lgp = logits + (size_t)seq * T_ * NUM_;

    // ---- gold score partial (512 threads stride over time) ----
    float gpart = 0.f;
    {
        const int* lab = labels + seq * T_;
        for (int t = tid; t < len; t += 512){
            int l1 = lab[t];
            gpart += lgp[(size_t)t * NUM_ + l1];
            int l0 = (t == 0) ? (L_ - 2) : lab[t - 1];
            gpart += trans[l1 * L_ + l0];
        }
        if (tid == 0) gpart += trans[(L_ - 1) * L_ + lab[len - 1]];
    }

    // ---- init p0 in all 4 replicas of buffer 0 ----
    pbuf[0][REPF * q + j] = (j == (L_ - 2)) ? 1.f : 0.f;
    __syncthreads();

    const bool lab_ok = (j < NUM_);
    float lgbuf[4];
    #pragma unroll
    for (int k = 0; k < 4; k++)
        lgbuf[k] = lab_ok ? __ldg(lgp + (size_t)k * NUM_ + j) : -1.0e30f;

    float c    = 0.f;   // accumulated log-scale
    float pend = 1.f;   // pending 1/m from last renormalization
    int   t0   = 0;

    // ---- main scan: 4-step blocks, renorm every 4th step, prefetch 4 ahead ----
    while (t0 + 4 <= len){
        float nbuf[4];
        #pragma unroll
        for (int k = 0; k < 4; k++){
            int tp = t0 + 4 + k;
            nbuf[k] = (lab_ok && tp < T_) ? __ldg(lgp + (size_t)tp * NUM_ + j) : -1.0e30f;
        }
        #pragma unroll
        for (int k = 0; k < 4; k++){
            const float* src = pbuf[k & 1] + 164 * q;   // replica q, its own 32-chunk
            float s = dot32(src, Ereg);
            s += __shfl_xor_sync(0xffffffffu, s, 1);    // combine quarters
            s += __shfl_xor_sync(0xffffffffu, s, 2);
            float u = __expf(lgbuf[k]);                 // pad labels -> 0
            float v = s * u;
            if (k == 0) v *= pend;
            if (k == 3){
                float mw = v;                           // warp max over the 8 labels
                mw = fmaxf(mw, __shfl_xor_sync(0xffffffffu, mw, 4));
                mw = fmaxf(mw, __shfl_xor_sync(0xffffffffu, mw, 8));
                mw = fmaxf(mw, __shfl_xor_sync(0xffffffffu, mw, 16));
                if (lane == 0) red[w] = mw;
            }
            pbuf[(k & 1) ^ 1][REPF * q + j] = v;        // write own replica
            __syncthreads();
            if (k == 3){
                const float4* r4 = (const float4*)red;
                float4 ra = r4[0], rb = r4[1], rc = r4[2], rd = r4[3];
                float m = fmaxf(fmaxf(fmaxf(fmaxf(ra.x, ra.y), fmaxf(ra.z, ra.w)),
                                      fmaxf(fmaxf(rb.x, rb.y), fmaxf(rb.z, rb.w))),
                                fmaxf(fmaxf(fmaxf(rc.x, rc.y), fmaxf(rc.z, rc.w)),
                                      fmaxf(fmaxf(rd.x, rd.y), fmaxf(rd.z, rd.w))));
                pend = __fdividef(1.f, m);
                c += __logf(m);
            }
        }
        #pragma unroll
        for (int k = 0; k < 4; k++) lgbuf[k] = nbuf[k];
        t0 += 4;
    }

    // ---- remainder (0..3 steps), renorm every step ----
    int rem = len - t0;
    #pragma unroll
    for (int k = 0; k < 3; k++){
        if (k < rem){
            const float* src = pbuf[k & 1] + 164 * q;
            float s = dot32(src, Ereg);
            s += __shfl_xor_sync(0xffffffffu, s, 1);
            s += __shfl_xor_sync(0xffffffffu, s, 2);
            float u = __expf(lgbuf[k]);
            float v = s * u * pend;
            float mw = v;
            mw = fmaxf(mw, __shfl_xor_sync(0xffffffffu, mw, 4));
            mw = fmaxf(mw, __shfl_xor_sync(0xffffffffu, mw, 8));
            mw = fmaxf(mw, __shfl_xor_sync(0xffffffffu, mw, 16));
            if (lane == 0) red[w] = mw;
            pbuf[(k & 1) ^ 1][REPF * q + j] = v;
            __syncthreads();
            const float4* r4 = (const float4*)red;
            float4 ra = r4[0], rb = r4[1], rc = r4[2], rd = r4[3];
            float m = fmaxf(fmaxf(fmaxf(fmaxf(ra.x, ra.y), fmaxf(ra.z, ra.w)),
                                  fmaxf(fmaxf(rb.x, rb.y), fmaxf(rb.z, rb.w))),
                            fmaxf(fmaxf(fmaxf(rc.x, rc.y), fmaxf(rc.z, rc.w)),
                                  fmaxf(fmaxf(rd.x, rd.y), fmaxf(rd.z, rd.w))));
            pend = __fdividef(1.f, m);
            c += __logf(m);
        }
    }

    // ---- epilogue ----
    __syncthreads();   // protect red[] of last renorm before reuse
    const float* pf = pbuf[len & 1];   // replica 0 holds p[0..127] at offset 0
    float term = (tid < L_) ? pf[tid] * __expf(trans[(L_ - 1) * L_ + tid]) : 0.f;
    #pragma unroll
    for (int o = 16; o; o >>= 1){
        term  += __shfl_xor_sync(0xffffffffu, term,  o);
        gpart += __shfl_xor_sync(0xffffffffu, gpart, o);
    }
    if (lane == 0){ red[w] = term; red2[w] = gpart; }
    __syncthreads();
    if (tid == 0){
        float S = 0.f, G = 0.f;
        #pragma unroll
        for (int i = 0; i < 16; i++){ S += red[i]; G += red2[i]; }
        out[seq] = G - (c + __logf(S * pend));
    }
}

extern "C" void kernel_launch(void* const* d_in, const int* in_sizes, int n_in,
                              void* d_out, int out_size)
{
    (void)in_sizes; (void)n_in; (void)out_size;
    const float* logits = (const float*)d_in[0];
    const int*   labels = (const int*)d_in[1];
    const int*   lens   = (const int*)d_in[2];
    const float* trans  = (const float*)d_in[3];
    float*       out    = (float*)d_out;

    crf_sort_kernel<<<1, B_>>>(lens);
    crf_main_kernel<<<B_, 512>>>(logits, labels, lens, trans, out);
}

// round 6
// speedup vs baseline: 1.3720x; 1.3720x over previous
#include <cuda_runtime.h>

#define B_   256
#define T_   1024
#define NUM_ 126
#define L_   128
#define QS   36    // floats per quarter slot: 32 data + 4 pad -> quarter q starts at bank 4q

__device__ int d_perm[B_];

// Rank-sort sequences by length (descending), deterministic, O(n^2) with n=256.
__global__ void crf_sort_kernel(const int* __restrict__ lens){
    __shared__ int sl[B_];
    int i = threadIdx.x;
    sl[i] = lens[i];
    __syncthreads();
    int v = sl[i];
    int r = 0;
    #pragma unroll 8
    for (int j = 0; j < B_; j++){
        int w = sl[j];
        r += (int)((w > v) | ((w == v) & (j < i)));
    }
    d_perm[r] = i;
}

__device__ __forceinline__ void ffma2(unsigned long long &d, unsigned long long a, unsigned long long b){
    asm volatile("fma.rn.f32x2 %0, %1, %2, %0;" : "+l"(d) : "l"(a), "l"(b));
}
__device__ __forceinline__ unsigned long long fadd2(unsigned long long a, unsigned long long b){
    unsigned long long d;
    asm volatile("add.rn.f32x2 %0, %1, %2;" : "=l"(d) : "l"(a), "l"(b));
    return d;
}
__device__ __forceinline__ float sum2(unsigned long long s2){
    return __uint_as_float((unsigned)(s2 & 0xffffffffull)) +
           __uint_as_float((unsigned)(s2 >> 32));
}

#define GBAR(id) asm volatile("bar.sync %0, 128;" :: "r"(id) : "memory")

__global__ void __launch_bounds__(256, 1)
crf_main_kernel(const float* __restrict__ logits,
                const int*   __restrict__ labels,
                const int*   __restrict__ lens,
                const float* __restrict__ trans,
                float*       __restrict__ out)
{
    __shared__ __align__(16) float pbuf_all[2][2][4 * QS];
    __shared__ float red_all[2][8];

    const int tid   = threadIdx.x;
    const int grp   = tid >> 7;          // 0/1: two independent sequence groups
    const int gt    = tid & 127;         // thread index inside group
    const int lane  = gt & 31;
    const int w     = gt >> 5;           // warp in group (0..3); owns labels [32w, 32w+32)
    const int q     = lane & 3;          // quarter of i-range: i in [32q, 32q+32)
    const int lg8   = lane >> 2;         // 0..7
    const int barid = 1 + grp;

    // This thread computes partial dots for 4 labels; it WRITES label_own (k = q).
    const int labbase   = w * 32 + lg8;          // label for k: labbase + 8k
    const int label_own = labbase + 8 * q;

    // Pair longest with shortest inside the CTA.
    const int rank = (grp == 0) ? (int)blockIdx.x : (B_ - 1 - (int)blockIdx.x);
    const int seq  = d_perm[rank];
    const int len  = lens[seq];

    float (*pb)[4 * QS] = pbuf_all[grp];
    float* red          = red_all[grp];

    // ---- E quarter-rows: exp(Tr[labbase+8k, 32q .. 32q+32)) -> 4 x 16 packed f32x2 ----
    unsigned long long E0[16], E1[16], E2[16], E3[16];
    {
        #pragma unroll
        for (int m = 0; m < 16; m++){
            const float* t0 = trans + (labbase     ) * L_ + 32 * q + 2 * m;
            const float* t1 = trans + (labbase +  8) * L_ + 32 * q + 2 * m;
            const float* t2 = trans + (labbase + 16) * L_ + 32 * q + 2 * m;
            const float* t3 = trans + (labbase + 24) * L_ + 32 * q + 2 * m;
            E0[m] = (unsigned long long)__float_as_uint(expf(t0[0])) | ((unsigned long long)__float_as_uint(expf(t0[1])) << 32);
            E1[m] = (unsigned long long)__float_as_uint(expf(t1[0])) | ((unsigned long long)__float_as_uint(expf(t1[1])) << 32);
            E2[m] = (unsigned long long)__float_as_uint(expf(t2[0])) | ((unsigned long long)__float_as_uint(expf(t2[1])) << 32);
            E3[m] = (unsigned long long)__float_as_uint(expf(t3[0])) | ((unsigned long long)__float_as_uint(expf(t3[1])) << 32);
        }
    }

    const float* lgp = logits + (size_t)seq * T_ * NUM_;

    // ---- gold score partial (group threads stride over time) ----
    float gpart = 0.f;
    {
        const int* lab = labels + seq * T_;
        for (int t = gt; t < len; t += 128){
            int l1 = lab[t];
            gpart += lgp[(size_t)t * NUM_ + l1];
            int l0 = (t == 0) ? (L_ - 2) : lab[t - 1];
            gpart += trans[l1 * L_ + l0];
        }
        if (gt == 0) gpart += trans[(L_ - 1) * L_ + lab[len - 1]];
    }

    // ---- init p0: thread writes its own label slot (layout: quarter-slotted, skewed) ----
    pb[0][QS * w + (label_own & 31)] = (label_own == (L_ - 2)) ? 1.f : 0.f;
    GBAR(barid);

    const bool lab_ok = (label_own < NUM_);
    float lgbuf[4];
    #pragma unroll
    for (int k = 0; k < 4; k++)
        lgbuf[k] = lab_ok ? __ldg(lgp + (size_t)k * NUM_ + label_own) : -1.0e30f;

    float c    = 0.f;   // accumulated log-scale
    float pend = 1.f;   // pending 1/m from last renormalization
    int   t0   = 0;

    // ================= main scan: 4-step blocks, renorm every 4th, prefetch 4 ahead ======
    while (t0 + 4 <= len){
        float nbuf[4];
        #pragma unroll
        for (int k = 0; k < 4; k++){
            int tp = t0 + 4 + k;
            nbuf[k] = (lab_ok && tp < T_) ? __ldg(lgp + (size_t)tp * NUM_ + label_own) : -1.0e30f;
        }
        #pragma unroll
        for (int k = 0; k < 4; k++){
            // quarter dot for 4 labels: 8 LDS.128, 64 FFMA2
            const ulonglong2* pd = (const ulonglong2*)(pb[k & 1] + QS * q);
            unsigned long long a00 = 0ull, a01 = 0ull, a10 = 0ull, a11 = 0ull;
            unsigned long long a20 = 0ull, a21 = 0ull, a30 = 0ull, a31 = 0ull;
            #pragma unroll
            for (int i = 0; i < 8; i++){
                ulonglong2 pv = pd[i];
                ffma2(a00, E0[2*i], pv.x); ffma2(a01, E0[2*i+1], pv.y);
                ffma2(a10, E1[2*i], pv.x); ffma2(a11, E1[2*i+1], pv.y);
                ffma2(a20, E2[2*i], pv.x); ffma2(a21, E2[2*i+1], pv.y);
                ffma2(a30, E3[2*i], pv.x); ffma2(a31, E3[2*i+1], pv.y);
            }
            float s0 = sum2(fadd2(a00, a01));
            float s1 = sum2(fadd2(a10, a11));
            float s2 = sum2(fadd2(a20, a21));
            float s3 = sum2(fadd2(a30, a31));
            // combine quarters across the quad (lanes differing in bits 0,1 of lane id)
            s0 += __shfl_xor_sync(0xffffffffu, s0, 1);
            s1 += __shfl_xor_sync(0xffffffffu, s1, 1);
            s2 += __shfl_xor_sync(0xffffffffu, s2, 1);
            s3 += __shfl_xor_sync(0xffffffffu, s3, 1);
            s0 += __shfl_xor_sync(0xffffffffu, s0, 2);
            s1 += __shfl_xor_sync(0xffffffffu, s1, 2);
            s2 += __shfl_xor_sync(0xffffffffu, s2, 2);
            s3 += __shfl_xor_sync(0xffffffffu, s3, 2);
            // this lane finalizes label_own = labbase + 8q
            float sv = (q == 0) ? s0 : (q == 1) ? s1 : (q == 2) ? s2 : s3;
            float v  = sv * __expf(lgbuf[k]);          // pad labels -> exp(-1e30) = 0
            if (k == 0) v *= pend;
            if (k == 3){
                float mw = v;
                #pragma unroll
                for (int o = 16; o; o >>= 1)
                    mw = fmaxf(mw, __shfl_xor_sync(0xffffffffu, mw, o));
                if (lane == 0) red[w] = mw;
            }
            pb[(k & 1) ^ 1][QS * w + (label_own & 31)] = v;   // conflict-free STS.32
            GBAR(barid);
            if (k == 3){
                float m = fmaxf(fmaxf(red[0], red[1]), fmaxf(red[2], red[3]));
                pend = __fdividef(1.f, m);
                c += __logf(m);
            }
        }
        #pragma unroll
        for (int k = 0; k < 4; k++) lgbuf[k] = nbuf[k];
        t0 += 4;
    }

    // ---- remainder (0..3 steps), renorm every step ----
    int rem = len - t0;
    #pragma unroll
    for (int k = 0; k < 3; k++){
        if (k < rem){
            const ulonglong2* pd = (const ulonglong2*)(pb[k & 1] + QS * q);
            unsigned long long a00 = 0ull, a01 = 0ull, a10 = 0ull, a11 = 0ull;
            unsigned long long a20 = 0ull, a21 = 0ull, a30 = 0ull, a31 = 0ull;
            #pragma unroll
            for (int i = 0; i < 8; i++){
                ulonglong2 pv = pd[i];
                ffma2(a00, E0[2*i], pv.x); ffma2(a01, E0[2*i+1], pv.y);
                ffma2(a10, E1[2*i], pv.x); ffma2(a11, E1[2*i+1], pv.y);
                ffma2(a20, E2[2*i], pv.x); ffma2(a21, E2[2*i+1], pv.y);
                ffma2(a30, E3[2*i], pv.x); ffma2(a31, E3[2*i+1], pv.y);
            }
            float s0 = sum2(fadd2(a00, a01));
            float s1 = sum2(fadd2(a10, a11));
            float s2 = sum2(fadd2(a20, a21));
            float s3 = sum2(fadd2(a30, a31));
            s0 += __shfl_xor_sync(0xffffffffu, s0, 1);
            s1 += __shfl_xor_sync(0xffffffffu, s1, 1);
            s2 += __shfl_xor_sync(0xffffffffu, s2, 1);
            s3 += __shfl_xor_sync(0xffffffffu, s3, 1);
            s0 += __shfl_xor_sync(0xffffffffu, s0, 2);
            s1 += __shfl_xor_sync(0xffffffffu, s1, 2);
            s2 += __shfl_xor_sync(0xffffffffu, s2, 2);
            s3 += __shfl_xor_sync(0xffffffffu, s3, 2);
            float sv = (q == 0) ? s0 : (q == 1) ? s1 : (q == 2) ? s2 : s3;
            float v  = sv * __expf(lgbuf[k]) * pend;
            float mw = v;
            #pragma unroll
            for (int o = 16; o; o >>= 1)
                mw = fmaxf(mw, __shfl_xor_sync(0xffffffffu, mw, o));
            if (lane == 0) red[w] = mw;
            pb[(k & 1) ^ 1][QS * w + (label_own & 31)] = v;
            GBAR(barid);
            float m = fmaxf(fmaxf(red[0], red[1]), fmaxf(red[2], red[3]));
            pend = __fdividef(1.f, m);
            c += __logf(m);
        }
    }

    // ---- epilogue ----
    GBAR(barid);   // protect red[] of last renorm before reuse
    const float* pf = pb[rem & 1];
    float term = pf[QS * (gt >> 5) + (gt & 31)] * __expf(trans[(L_ - 1) * L_ + gt]);
    #pragma unroll
    for (int o = 16; o; o >>= 1){
        term  += __shfl_xor_sync(0xffffffffu, term,  o);
        gpart += __shfl_xor_sync(0xffffffffu, gpart, o);
    }
    if (lane == 0){ red[w] = term; red[4 + w] = gpart; }
    GBAR(barid);
    if (gt == 0){
        float S = red[0] + red[1] + red[2] + red[3];
        float G = red[4] + red[5] + red[6] + red[7];
        out[seq] = G - (c + __logf(S * pend));
    }
}

extern "C" void kernel_launch(void* const* d_in, const int* in_sizes, int n_in,
                              void* d_out, int out_size)
{
    (void)in_sizes; (void)n_in; (void)out_size;
    const float* logits = (const float*)d_in[0];
    const int*   labels = (const int*)d_in[1];
    const int*   lens   = (const int*)d_in[2];
    const float* trans  = (const float*)d_in[3];
    float*       out    = (float*)d_out;

    crf_sort_kernel<<<1, B_>>>(lens);
    crf_main_kernel<<<B_ / 2, 256>>>(logits, labels, lens, trans, out);
}

// round 7
// speedup vs baseline: 1.4222x; 1.0366x over previous
#include <cuda_runtime.h>

#define B_    256
#define T_    1024
#define NUM_  126
#define L_    128
#define HOFF  68     // float offset of half-1 in p buffer (272B) -> bank-group skew of 4
#define PBUF  136

__device__ int d_perm[B_];

// Rank-sort sequences by length (descending), deterministic, O(n^2) with n=256.
__global__ void crf_sort_kernel(const int* __restrict__ lens){
    __shared__ int sl[B_];
    int i = threadIdx.x;
    sl[i] = lens[i];
    __syncthreads();
    int v = sl[i];
    int r = 0;
    #pragma unroll 8
    for (int j = 0; j < B_; j++){
        int w = sl[j];
        r += (int)((w > v) | ((w == v) & (j < i)));
    }
    d_perm[r] = i;
}

__device__ __forceinline__ void ffma2(unsigned long long &d, unsigned long long a, unsigned long long b){
    asm volatile("fma.rn.f32x2 %0, %1, %2, %0;" : "+l"(d) : "l"(a), "l"(b));
}
__device__ __forceinline__ unsigned long long fadd2(unsigned long long a, unsigned long long b){
    unsigned long long d;
    asm volatile("add.rn.f32x2 %0, %1, %2;" : "=l"(d) : "l"(a), "l"(b));
    return d;
}

// Half dot: s = sum_{i<64} E[i]*p[i]; E = 32 packed f32x2 regs; p broadcast
// (all even lanes one address, all odd lanes one address, disjoint bank groups).
__device__ __forceinline__ float dot64(const float* __restrict__ p, const unsigned long long* __restrict__ E){
    const ulonglong2* pd = (const ulonglong2*)p;   // 16 x 16B
    unsigned long long a0 = 0ull, a1 = 0ull, a2 = 0ull, a3 = 0ull;
    #pragma unroll
    for (int i = 0; i < 16; i += 2){
        ulonglong2 q0 = pd[i];
        ulonglong2 q1 = pd[i + 1];
        ffma2(a0, E[2*i + 0], q0.x);
        ffma2(a1, E[2*i + 1], q0.y);
        ffma2(a2, E[2*i + 2], q1.x);
        ffma2(a3, E[2*i + 3], q1.y);
    }
    unsigned long long s2 = fadd2(fadd2(a0, a1), fadd2(a2, a3));
    return __uint_as_float((unsigned)(s2 & 0xffffffffull)) +
           __uint_as_float((unsigned)(s2 >> 32));
}

__device__ __forceinline__ int slot(int j){ return j + ((j >= 64) ? (HOFF - 64) : 0); }

__global__ void __launch_bounds__(256, 2)
crf_main_kernel(const float* __restrict__ logits,
                const int*   __restrict__ labels,
                const int*   __restrict__ lens,
                const float* __restrict__ trans,
                float*       __restrict__ out)
{
    __shared__ __align__(16) float pbuf[2][PBUF];
    __shared__ float red[8];
    __shared__ float red2[8];

    const int tid  = threadIdx.x;
    const int j    = tid >> 1;        // label owned by this lane pair
    const int half = tid & 1;         // 0: i in [0,64), 1: i in [64,128)
    const int lane = tid & 31;
    const int w    = tid >> 5;        // warp 0..7

    // Classic placement: bid and bid+148 land on the same SM -> pair long+short.
    const int bid  = (int)blockIdx.x;
    const int rank = (bid < 148) ? bid : (403 - bid);
    const int seq  = d_perm[rank];
    const int len  = lens[seq];

    // ---- E half-row exp(Tr[j, 64*half .. +64)) in 32 packed f32x2 regs ----
    unsigned long long Ereg[32];
    {
        const float* trow = trans + j * L_ + half * 64;
        #pragma unroll
        for (int m = 0; m < 32; m++){
            float e0 = expf(trow[2*m]);
            float e1 = expf(trow[2*m + 1]);
            Ereg[m] = (unsigned long long)__float_as_uint(e0)
                    | ((unsigned long long)__float_as_uint(e1) << 32);
        }
    }

    const float* lgp = logits + (size_t)seq * T_ * NUM_;

    // ---- gold score partial (256 threads stride over time) ----
    float gpart = 0.f;
    {
        const int* lab = labels + seq * T_;
        for (int t = tid; t < len; t += 256){
            int l1 = lab[t];
            gpart += lgp[(size_t)t * NUM_ + l1];
            int l0 = (t == 0) ? (L_ - 2) : lab[t - 1];
            gpart += trans[l1 * L_ + l0];
        }
        if (tid == 0) gpart += trans[(L_ - 1) * L_ + lab[len - 1]];
    }

    // ---- init p0 ----
    if (!half) pbuf[0][slot(j)] = (j == (L_ - 2)) ? 1.f : 0.f;
    __syncthreads();

    const bool lab_ok = (j < NUM_);
    float lgbuf[4];
    #pragma unroll
    for (int k = 0; k < 4; k++)
        lgbuf[k] = lab_ok ? __ldg(lgp + (size_t)k * NUM_ + j) : -1.0e30f;

    float c    = 0.f;   // accumulated log-scale
    float pend = 1.f;   // pending 1/m from last renormalization
    int   t0   = 0;

    const float* psrc0 = pbuf[0] + half * HOFF;
    const float* psrc1 = pbuf[1] + half * HOFF;

    // ===== main scan: 4-step blocks, renorm every 4th step, prefetch 4 ahead =====
    while (t0 + 4 <= len){
        float nbuf[4];
        #pragma unroll
        for (int k = 0; k < 4; k++){
            int tp = t0 + 4 + k;
            nbuf[k] = (lab_ok && tp < T_) ? __ldg(lgp + (size_t)tp * NUM_ + j) : -1.0e30f;
        }
        #pragma unroll
        for (int k = 0; k < 4; k++){
            float s = dot64((k & 1) ? psrc1 : psrc0, Ereg);
            s += __shfl_xor_sync(0xffffffffu, s, 1);      // combine halves (both lanes get full s)
            float v = s * __expf(lgbuf[k]);               // pad labels -> exp(-1e30) = 0
            if (k == 0) v *= pend;
            if (k == 3){
                float mw = v;                             // warp max over its 16 labels (dup lanes ok)
                #pragma unroll
                for (int o = 2; o <= 16; o <<= 1)
                    mw = fmaxf(mw, __shfl_xor_sync(0xffffffffu, mw, o));
                if (lane == 0) red[w] = mw;
            }
            if (!half) pbuf[(k & 1) ^ 1][slot(j)] = v;    // conflict-free STS.32
            __syncthreads();
            if (k == 3){
                const float4* r4 = (const float4*)red;
                float4 ra = r4[0], rb = r4[1];
                float m = fmaxf(fmaxf(fmaxf(ra.x, ra.y), fmaxf(ra.z, ra.w)),
                                fmaxf(fmaxf(rb.x, rb.y), fmaxf(rb.z, rb.w)));
                pend = __fdividef(1.f, m);
                c += __logf(m);
            }
        }
        #pragma unroll
        for (int k = 0; k < 4; k++) lgbuf[k] = nbuf[k];
        t0 += 4;
    }

    // ---- remainder (0..3 steps), renorm every step ----
    int rem = len - t0;
    #pragma unroll
    for (int k = 0; k < 3; k++){
        if (k < rem){
            float s = dot64((k & 1) ? psrc1 : psrc0, Ereg);
            s += __shfl_xor_sync(0xffffffffu, s, 1);
            float v = s * __expf(lgbuf[k]) * pend;
            float mw = v;
            #pragma unroll
            for (int o = 2; o <= 16; o <<= 1)
                mw = fmaxf(mw, __shfl_xor_sync(0xffffffffu, mw, o));
            if (lane == 0) red[w] = mw;
            if (!half) pbuf[(k & 1) ^ 1][slot(j)] = v;
            __syncthreads();
            const float4* r4 = (const float4*)red;
            float4 ra = r4[0], rb = r4[1];
            float m = fmaxf(fmaxf(fmaxf(ra.x, ra.y), fmaxf(ra.z, ra.w)),
                            fmaxf(fmaxf(rb.x, rb.y), fmaxf(rb.z, rb.w)));
            pend = __fdividef(1.f, m);
            c += __logf(m);
        }
    }

    // ---- epilogue ----
    __syncthreads();   // protect red[] of last renorm before reuse
    const float* pf = pbuf[len & 1];
    float term = (tid < L_) ? pf[slot(tid)] * __expf(trans[(L_ - 1) * L_ + tid]) : 0.f;
    #pragma unroll
    for (int o = 16; o; o >>= 1){
        term  += __shfl_xor_sync(0xffffffffu, term,  o);
        gpart += __shfl_xor_sync(0xffffffffu, gpart, o);
    }
    if (lane == 0){ red[w] = term; red2[w] = gpart; }
    __syncthreads();
    if (tid == 0){
        float S = 0.f, G = 0.f;
        #pragma unroll
        for (int i = 0; i < 8; i++){ S += red[i]; G += red2[i]; }
        out[seq] = G - (c + __logf(S * pend));
    }
}

extern "C" void kernel_launch(void* const* d_in, const int* in_sizes, int n_in,
                              void* d_out, int out_size)
{
    (void)in_sizes; (void)n_in; (void)out_size;
    const float* logits = (const float*)d_in[0];
    const int*   labels = (const int*)d_in[1];
    const int*   lens   = (const int*)d_in[2];
    const float* trans  = (const float*)d_in[3];
    float*       out    = (float*)d_out;

    crf_sort_kernel<<<1, B_>>>(lens);
    crf_main_kernel<<<B_, 256>>>(logits, labels, lens, trans, out);
}

// round 8
// speedup vs baseline: 1.5114x; 1.0627x over previous
#include <cuda_runtime.h>

#define B_    256
#define T_    1024
#define NUM_  126
#define L_    128

__device__ int d_perm[B_];

// Rank-sort sequences by length (descending), deterministic, O(n^2) with n=256.
__global__ void crf_sort_kernel(const int* __restrict__ lens){
    __shared__ int sl[B_];
    int i = threadIdx.x;
    sl[i] = lens[i];
    __syncthreads();
    int v = sl[i];
    int r = 0;
    #pragma unroll 8
    for (int j = 0; j < B_; j++){
        int w = sl[j];
        r += (int)((w > v) | ((w == v) & (j < i)));
    }
    d_perm[r] = i;
}

__device__ __forceinline__ void ffma2(unsigned long long &d, unsigned long long a, unsigned long long b){
    asm volatile("fma.rn.f32x2 %0, %1, %2, %0;" : "+l"(d) : "l"(a), "l"(b));
}
__device__ __forceinline__ unsigned long long fadd2(unsigned long long a, unsigned long long b){
    unsigned long long d;
    asm volatile("add.rn.f32x2 %0, %1, %2;" : "=l"(d) : "l"(a), "l"(b));
    return d;
}

// Warp max of a NON-NEGATIVE float in one instruction (bit pattern is s32-monotonic).
__device__ __forceinline__ float redux_max_pos(float v){
    int r;
    asm volatile("redux.sync.max.s32 %0, %1, 0xffffffff;" : "=r"(r) : "r"(__float_as_int(v)));
    return __int_as_float(r);
}

// Full dot: s = sum_{i<128} E[i]*p[i]; E = 64 packed f32x2 regs; p pure broadcast.
__device__ __forceinline__ float dot128(const float* __restrict__ p, const unsigned long long* __restrict__ E){
    const ulonglong2* pd = (const ulonglong2*)p;   // 32 x 16B, same addr across all lanes
    unsigned long long a0 = 0ull, a1 = 0ull, a2 = 0ull, a3 = 0ull;
    #pragma unroll
    for (int i = 0; i < 32; i += 2){
        ulonglong2 q0 = pd[i];
        ulonglong2 q1 = pd[i + 1];
        ffma2(a0, E[2*i + 0], q0.x);
        ffma2(a1, E[2*i + 1], q0.y);
        ffma2(a2, E[2*i + 2], q1.x);
        ffma2(a3, E[2*i + 3], q1.y);
    }
    unsigned long long s2 = fadd2(fadd2(a0, a1), fadd2(a2, a3));
    return __uint_as_float((unsigned)(s2 & 0xffffffffull)) +
           __uint_as_float((unsigned)(s2 >> 32));
}

__global__ void __launch_bounds__(128, 2)
crf_main_kernel(const float* __restrict__ logits,
                const int*   __restrict__ labels,
                const int*   __restrict__ lens,
                const float* __restrict__ trans,
                float*       __restrict__ out)
{
    __shared__ __align__(16) float pbuf[2][L_];
    __shared__ __align__(16) float red[2][4];     // per-warp maxima, double-buffered
    __shared__ float red2[8];

    const int jt   = threadIdx.x;     // label owned by this thread (0..127)
    const int lane = jt & 31;
    const int w    = jt >> 5;         // warp 0..3

    // Classic placement: bid and bid+148 share an SM -> long pairs with short.
    const int bid  = (int)blockIdx.x;
    const int rank = (bid < 148) ? bid : (403 - bid);
    const int seq  = d_perm[rank];
    const int len  = lens[seq];

    // ---- E row exp(Tr[jt, 0..128)) in 64 packed f32x2 regs ----
    unsigned long long Ereg[64];
    {
        const float* trow = trans + jt * L_;
        #pragma unroll
        for (int m = 0; m < 64; m++){
            float e0 = expf(trow[2*m]);
            float e1 = expf(trow[2*m + 1]);
            Ereg[m] = (unsigned long long)__float_as_uint(e0)
                    | ((unsigned long long)__float_as_uint(e1) << 32);
        }
    }

    const float* lgp = logits + (size_t)seq * T_ * NUM_;

    // ---- gold score partial (128 threads stride over time) ----
    float gpart = 0.f;
    {
        const int* lab = labels + seq * T_;
        for (int t = jt; t < len; t += 128){
            int l1 = lab[t];
            gpart += lgp[(size_t)t * NUM_ + l1];
            int l0 = (t == 0) ? (L_ - 2) : lab[t - 1];
            gpart += trans[l1 * L_ + l0];
        }
        if (jt == 0) gpart += trans[(L_ - 1) * L_ + lab[len - 1]];
    }

    // ---- init p0 and red ----
    pbuf[0][jt] = (jt == (L_ - 2)) ? 1.f : 0.f;
    if (jt < 8) red[jt >> 2][jt & 3] = 1.f;
    __syncthreads();

    const bool lab_ok = (jt < NUM_);

    // u = exp(logit) prefetched 4 steps ahead, converted off the critical chain.
    float ubuf[4];
    #pragma unroll
    for (int k = 0; k < 4; k++)
        ubuf[k] = lab_ok ? __expf(__ldg(lgp + (size_t)k * NUM_ + jt)) : 0.f;

    float c     = 0.f;   // sum of log M_t over all executed steps
    float r     = 1.f;   // 1/M_{t-1} (stale scale)
    float Mcur  = 1.f;   // M_t of the step just finished
    int   t     = 0;

    // ================= main scan: one step per iteration, unrolled 4 ==================
    #pragma unroll 4
    for (t = 0; t < len; t++){
        // prefetch logit for t+4 (LDG issued early, exp computed off-chain below)
        int tp = t + 4;
        float nlg = (lab_ok && tp < T_) ? __ldg(lgp + (size_t)tp * NUM_ + jt) : -1.0e30f;

        float s = dot128(pbuf[t & 1], Ereg);
        float v = s * ubuf[t & 3] * r;            // stale renorm scale
        float Mw = redux_max_pos(v);              // warp max, 1 instr
        if (lane == 0) red[t & 1][w] = Mw;
        pbuf[(t & 1) ^ 1][jt] = v;                // conflict-free STS.32
        ubuf[t & 3] = __expf(nlg);                // off-chain convert for t+4
        __syncthreads();
        // block max of this step (consumed NEXT step -> full step of slack)
        float4 rv = *(const float4*)red[t & 1];
        Mcur = fmaxf(fmaxf(rv.x, rv.y), fmaxf(rv.z, rv.w));
        r = __fdividef(1.f, Mcur);
        c += __logf(Mcur);
    }

    // ---- epilogue: a_len = q_len * prod_{s<=len-2} M_s  ->  norm = c - log(M_last) + log(S) ----
    const float* pf = pbuf[len & 1];
    float term = pf[jt] * __expf(trans[(L_ - 1) * L_ + jt]);
    #pragma unroll
    for (int o = 16; o; o >>= 1){
        term  += __shfl_xor_sync(0xffffffffu, term,  o);
        gpart += __shfl_xor_sync(0xffffffffu, gpart, o);
    }
    __syncthreads();   // red reuse safety
    if (lane == 0){ red[0][w] = term; red2[w] = gpart; }
    __syncthreads();
    if (jt == 0){
        float S = red[0][0] + red[0][1] + red[0][2] + red[0][3];
        float G = red2[0] + red2[1] + red2[2] + red2[3];
        out[seq] = G - (c - __logf(Mcur) + __logf(S));
    }
}

extern "C" void kernel_launch(void* const* d_in, const int* in_sizes, int n_in,
                              void* d_out, int out_size)
{
    (void)in_sizes; (void)n_in; (void)out_size;
    const float* logits = (const float*)d_in[0];
    const int*   labels = (const int*)d_in[1];
    const int*   lens   = (const int*)d_in[2];
    const float* trans  = (const float*)d_in[3];
    float*       out    = (float*)d_out;

    crf_sort_kernel<<<1, B_>>>(lens);
    crf_main_kernel<<<B_, 128>>>(logits, labels, lens, trans, out);
}

// round 9
// speedup vs baseline: 1.5403x; 1.0191x over previous
#include <cuda_runtime.h>

#define B_    256
#define T_    1024
#define NUM_  126
#define L_    128

__device__ int d_perm[B_];

// Rank-sort sequences by length (descending), deterministic, O(n^2) with n=256.
__global__ void crf_sort_kernel(const int* __restrict__ lens){
    __shared__ int sl[B_];
    int i = threadIdx.x;
    sl[i] = lens[i];
    __syncthreads();
    int v = sl[i];
    int r = 0;
    #pragma unroll 8
    for (int j = 0; j < B_; j++){
        int w = sl[j];
        r += (int)((w > v) | ((w == v) & (j < i)));
    }
    d_perm[r] = i;
}

__device__ __forceinline__ void ffma2(unsigned long long &d, unsigned long long a, unsigned long long b){
    asm volatile("fma.rn.f32x2 %0, %1, %2, %0;" : "+l"(d) : "l"(a), "l"(b));
}
__device__ __forceinline__ unsigned long long fadd2(unsigned long long a, unsigned long long b){
    unsigned long long d;
    asm volatile("add.rn.f32x2 %0, %1, %2;" : "=l"(d) : "l"(a), "l"(b));
    return d;
}

// Warp max of a NON-NEGATIVE float in one instruction (bits are s32-monotonic).
__device__ __forceinline__ float redux_max_pos(float v){
    int r;
    asm volatile("redux.sync.max.s32 %0, %1, 0xffffffff;" : "=r"(r) : "r"(__float_as_int(v)));
    return __int_as_float(r);
}

// Full dot: s = sum_{i<128} E[i]*p[i]; E = 64 packed f32x2 regs; p pure broadcast.
__device__ __forceinline__ float dot128(const float* __restrict__ p, const unsigned long long* __restrict__ E){
    const ulonglong2* pd = (const ulonglong2*)p;
    unsigned long long a0 = 0ull, a1 = 0ull, a2 = 0ull, a3 = 0ull;
    #pragma unroll
    for (int i = 0; i < 32; i += 2){
        ulonglong2 q0 = pd[i];
        ulonglong2 q1 = pd[i + 1];
        ffma2(a0, E[2*i + 0], q0.x);
        ffma2(a1, E[2*i + 1], q0.y);
        ffma2(a2, E[2*i + 2], q1.x);
        ffma2(a3, E[2*i + 3], q1.y);
    }
    unsigned long long s2 = fadd2(fadd2(a0, a1), fadd2(a2, a3));
    return __uint_as_float((unsigned)(s2 & 0xffffffffull)) +
           __uint_as_float((unsigned)(s2 >> 32));
}

__device__ __forceinline__ float blockmax4(const float* red){
    float4 rv = *(const float4*)red;
    return fmaxf(fmaxf(rv.x, rv.y), fmaxf(rv.z, rv.w));
}

#define GBAR(id) asm volatile("bar.sync %0, 128;" :: "r"(id) : "memory")

__global__ void __launch_bounds__(256, 1)
crf_main_kernel(const float* __restrict__ logits,
                const int*   __restrict__ labels,
                const int*   __restrict__ lens,
                const float* __restrict__ trans,
                float*       __restrict__ out)
{
    __shared__ __align__(16) float pbuf_all[2][2][L_];   // [group][parity][label]
    __shared__ __align__(16) float red_all[2][2][4];     // [group][parity][warp]
    __shared__ float scal[2];                            // cf', cb'
    __shared__ float redS[8], redG[8];

    const int tid  = threadIdx.x;
    const int grp  = tid >> 7;        // 0 = forward group, 1 = backward group
    const int jt   = tid & 127;       // label owned by this thread
    const int lane = tid & 31;
    const int w    = jt >> 5;         // warp within group (0..3)
    const int w8   = tid >> 5;        // warp within CTA (0..7)
    const int bid  = (int)blockIdx.x;

    const int seq = d_perm[bid];      // rank = bid (descending length)
    const int len = lens[seq];
    const int m   = len >> 1;         // forward steps
    const int K   = len - m;          // backward matvecs

    float (*pb)[L_] = pbuf_all[grp];
    float (*red)[4] = red_all[grp];

    // ---- E in registers: fwd = row jt of exp(Tr); bwd = column jt (transposed matvec) ----
    unsigned long long Ereg[64];
    #pragma unroll
    for (int q = 0; q < 64; q++){
        float e0, e1;
        if (grp == 0){
            e0 = expf(trans[jt * L_ + 2*q]);
            e1 = expf(trans[jt * L_ + 2*q + 1]);
        } else {
            e0 = expf(trans[(2*q    ) * L_ + jt]);
            e1 = expf(trans[(2*q + 1) * L_ + jt]);
        }
        Ereg[q] = (unsigned long long)__float_as_uint(e0)
                | ((unsigned long long)__float_as_uint(e1) << 32);
    }

    const float* lgp = logits + (size_t)seq * T_ * NUM_;

    // ---- gold score partial (all 256 threads stride over time) ----
    float gpart = 0.f;
    {
        const int* lab = labels + seq * T_;
        for (int t = tid; t < len; t += 256){
            int l1 = lab[t];
            gpart += lgp[(size_t)t * NUM_ + l1];
            int l0 = (t == 0) ? (L_ - 2) : lab[t - 1];
            gpart += trans[l1 * L_ + l0];
        }
        if (tid == 0) gpart += trans[(L_ - 1) * L_ + lab[len - 1]];
    }

    const bool lab_ok = (jt < NUM_);
    float c = 0.f, r = 1.f, Mcur = 1.f;
    float ubuf[4];

    if (grp == 0){
        // ================= FORWARD: a <- u_t * (E a), t = 0..m-1 =================
        pb[0][jt] = (jt == (L_ - 2)) ? 1.f : 0.f;
        GBAR(1);
        #pragma unroll
        for (int k = 0; k < 4; k++)
            ubuf[k] = lab_ok ? __expf(__ldg(lgp + (size_t)k * NUM_ + jt)) : 0.f;

        for (int t = 0; t < m; t++){
            int tp = t + 4;
            float nlg = (lab_ok && tp < T_) ? __ldg(lgp + (size_t)tp * NUM_ + jt) : -1.0e30f;
            float s = dot128(pb[t & 1], Ereg);
            float v = s * ubuf[t & 3] * r;             // stale renorm scale
            float Mw = redux_max_pos(v);
            if (lane == 0) red[t & 1][w] = Mw;
            pb[(t & 1) ^ 1][jt] = v;
            ubuf[t & 3] = __expf(nlg);
            GBAR(1);
            Mcur = blockmax4(red[t & 1]);
            r = __fdividef(1.f, Mcur);
            c += __logf(Mcur);
        }
        if (jt == 0) scal[0] = c - __logf(Mcur);       // m==0: 0 - log(1) = 0
    } else {
        // ================= BACKWARD: b <- E^T (u_t * b), t = len-1..m =================
        // z0 = u_{len-1} * w,  w[j] = exp(Tr[end, j])
        float wj = __expf(trans[(L_ - 1) * L_ + jt]);
        float ul = lab_ok ? __expf(__ldg(lgp + (size_t)(len - 1) * NUM_ + jt)) : 0.f;
        float v0 = ul * wj;
        float Mw0 = redux_max_pos(v0);
        if (lane == 0) red[0][w] = Mw0;
        pb[0][jt] = v0;
        GBAR(2);
        Mcur = blockmax4(red[0]);
        r = __fdividef(1.f, Mcur);
        c = __logf(Mcur);

        // ubuf[k&3] for iteration k holds u_{len-1-k}; iteration K uses 1.0 (no u).
        #pragma unroll
        for (int k = 1; k <= 4; k++){
            int uidx = len - 1 - k;
            float val;
            if (k == K)            val = 1.f;
            else if (k > K || uidx < 0) val = 0.f;     // unused
            else                   val = lab_ok ? __expf(__ldg(lgp + (size_t)uidx * NUM_ + jt)) : 0.f;
            ubuf[k & 3] = val;
        }

        for (int k = 1; k <= K; k++){
            int kp   = k + 4;
            int uidx = len - 1 - kp;
            float nlg = (kp == K) ? 0.f
                      : ((lab_ok && uidx >= 0) ? __ldg(lgp + (size_t)uidx * NUM_ + jt) : -1.0e30f);
            float s = dot128(pb[(k & 1) ^ 1], Ereg);
            float v = s * r * ubuf[k & 3];             // ubuf == 1 at k == K
            float Mw = redux_max_pos(v);
            if (lane == 0) red[k & 1][w] = Mw;
            pb[k & 1][jt] = v;
            ubuf[k & 3] = __expf(nlg);
            GBAR(2);
            Mcur = blockmax4(red[k & 1]);
            r = __fdividef(1.f, Mcur);
            c += __logf(Mcur);
        }
        if (jt == 0) scal[1] = c - __logf(Mcur);
    }

    // ================= merge: norm = log(sum_j A[j]*B[j]) + cf' + cb' =================
    __syncthreads();
    const float* A  = pbuf_all[0][m & 1];
    const float* Bv = pbuf_all[1][K & 1];
    float prod = (tid < L_) ? A[tid] * Bv[tid] : 0.f;
    #pragma unroll
    for (int o = 16; o; o >>= 1){
        prod  += __shfl_xor_sync(0xffffffffu, prod,  o);
        gpart += __shfl_xor_sync(0xffffffffu, gpart, o);
    }
    if (lane == 0){ redS[w8] = prod; redG[w8] = gpart; }
    __syncthreads();
    if (tid == 0){
        float S = 0.f, G = 0.f;
        #pragma unroll
        for (int i = 0; i < 8; i++){ S += redS[i]; G += redG[i]; }
        out[seq] = G - (__logf(S) + scal[0] + scal[1]);
    }
}

extern "C" void kernel_launch(void* const* d_in, const int* in_sizes, int n_in,
                              void* d_out, int out_size)
{
    (void)in_sizes; (void)n_in; (void)out_size;
    const float* logits = (const float*)d_in[0];
    const int*   labels = (const int*)d_in[1];
    const int*   lens   = (const int*)d_in[2];
    const float* trans  = (const float*)d_in[3];
    float*       out    = (float*)d_out;

    crf_sort_kernel<<<1, B_>>>(lens);
    crf_main_kernel<<<B_, 256>>>(logits, labels, lens, trans, out);
}